// round 3
// baseline (speedup 1.0000x reference)
#include <cuda_runtime.h>
#include <cuda_bf16.h>

// Problem constants (fixed by the reference setup_inputs)
#define BATCH 4
#define CH    256
#define HH    64
#define WW    64
#define NROI  256
#define PP    7        // pooled size == part size
#define SS    4        // samples per bin edge
#define SPATIAL_SCALE 0.125f
#define TRANS_STD     0.1f

// 16 MB NHWC scratch: g_nhwc[((b*H + y)*W + x)*C + c]
__device__ float g_nhwc[BATCH * HH * WW * CH];

// ---------------------------------------------------------------------------
// Kernel 1: NCHW -> NHWC transpose, smem-tiled, 4 elems/thread (MLP=4).
// Block (32,8), tile 32c x 32w per (b,h). Grid: (W/32, C/32, B*H)
// ---------------------------------------------------------------------------
__global__ __launch_bounds__(256) void nchw_to_nhwc_kernel(const float* __restrict__ data) {
    __shared__ float tile[32][33];
    const int bh = blockIdx.z;
    const int b  = bh / HH;
    const int h  = bh % HH;
    const int c0 = blockIdx.y * 32;
    const int w0 = blockIdx.x * 32;
    const int tx = threadIdx.x;
    const int ty = threadIdx.y;

    float v0 = data[((b * CH + (c0 + ty +  0)) * HH + h) * WW + (w0 + tx)];
    float v1 = data[((b * CH + (c0 + ty +  8)) * HH + h) * WW + (w0 + tx)];
    float v2 = data[((b * CH + (c0 + ty + 16)) * HH + h) * WW + (w0 + tx)];
    float v3 = data[((b * CH + (c0 + ty + 24)) * HH + h) * WW + (w0 + tx)];
    tile[ty +  0][tx] = v0;
    tile[ty +  8][tx] = v1;
    tile[ty + 16][tx] = v2;
    tile[ty + 24][tx] = v3;
    __syncthreads();
    #pragma unroll
    for (int i = 0; i < 4; i++) {
        g_nhwc[((b * HH + h) * WW + (w0 + ty + 8 * i)) * CH + (c0 + tx)] = tile[tx][ty + 8 * i];
    }
}

// ---------------------------------------------------------------------------
// Kernel 2: deformable RoI pooling, separable weights + unconditional 4x4
// gather with clamped addresses for max MLP.
// One block = one (roi n, ph) row: 7 bins (pw) x 64 channel-quad threads = 448.
// ---------------------------------------------------------------------------
struct BinInfo {
    float wx[4];
    float wy[4];
    float inv;
    int xbase, ybase, b;
};

__global__ __launch_bounds__(448, 2) void deform_roi_pool_kernel(
    const float* __restrict__ rois,
    const float* __restrict__ offset,
    float* __restrict__ out)
{
    __shared__ BinInfo sbin[PP];
    __shared__ float4  sm4[PP * 64];   // [pw][c4] result staging

    const int ph = blockIdx.x;          // 0..6
    const int n  = blockIdx.y;          // 0..255
    const int tid   = threadIdx.x;
    const int group = tid >> 6;         // pw, 0..6
    const int c4    = tid & 63;         // channel quad

    // ---------------- Phase 1: per-bin separable weights (leader threads) ----
    if (c4 == 0) {
        const int pw = group;
        const int r  = ph * PP + pw;
        const float* roi = rois + n * 5;
        const int   b      = (int)roi[0];
        const float roi_sw = rintf(roi[1]) * SPATIAL_SCALE - 0.5f;
        const float roi_sh = rintf(roi[2]) * SPATIAL_SCALE - 0.5f;
        const float roi_ew = (rintf(roi[3]) + 1.0f) * SPATIAL_SCALE - 0.5f;
        const float roi_eh = (rintf(roi[4]) + 1.0f) * SPATIAL_SCALE - 0.5f;
        const float roi_w  = fmaxf(roi_ew - roi_sw, 0.1f);
        const float roi_h  = fmaxf(roi_eh - roi_sh, 0.1f);
        const float bin_w  = roi_w / (float)PP;
        const float bin_h  = roi_h / (float)PP;
        const float sub_w  = bin_w / (float)SS;
        const float sub_h  = bin_h / (float)SS;

        const float tx_off = offset[(n * 2 + 0) * (PP * PP) + r] * TRANS_STD;
        const float ty_off = offset[(n * 2 + 1) * (PP * PP) + r] * TRANS_STD;

        const float wstart = (float)pw * bin_w + roi_sw + tx_off * roi_w;
        const float hstart = (float)ph * bin_h + roi_sh + ty_off * roi_h;

        // --- x direction ---
        float lwx[4] = {0.f, 0.f, 0.f, 0.f};
        int cw = 0, xb = 0;
        bool xset = false;
        #pragma unroll
        for (int s = 0; s < SS; s++) {
            const float wcoord = wstart + (float)s * sub_w;
            if (wcoord > -0.5f && wcoord < (float)WW - 0.5f) {
                cw++;
                const float wc = fminf(fmaxf(wcoord, 0.0f), (float)(WW - 1));
                const int x0 = (int)floorf(wc);
                if (!xset) { xb = x0; xset = true; }
                const float dx = wc - (float)x0;
                const int o0 = x0 - xb;
                const int o1 = min(x0 + 1, WW - 1) - xb;
                #pragma unroll
                for (int k = 0; k < 4; k++) {
                    lwx[k] += (o0 == k ? 1.0f - dx : 0.0f) + (o1 == k ? dx : 0.0f);
                }
            }
        }
        // --- y direction ---
        float lwy[4] = {0.f, 0.f, 0.f, 0.f};
        int chh = 0, yb = 0;
        bool yset = false;
        #pragma unroll
        for (int s = 0; s < SS; s++) {
            const float hcoord = hstart + (float)s * sub_h;
            if (hcoord > -0.5f && hcoord < (float)HH - 0.5f) {
                chh++;
                const float hc = fminf(fmaxf(hcoord, 0.0f), (float)(HH - 1));
                const int y0 = (int)floorf(hc);
                if (!yset) { yb = y0; yset = true; }
                const float dy = hc - (float)y0;
                const int o0 = y0 - yb;
                const int o1 = min(y0 + 1, HH - 1) - yb;
                #pragma unroll
                for (int k = 0; k < 4; k++) {
                    lwy[k] += (o0 == k ? 1.0f - dy : 0.0f) + (o1 == k ? dy : 0.0f);
                }
            }
        }

        const int cnt = cw * chh;
        BinInfo bi;
        #pragma unroll
        for (int k = 0; k < 4; k++) { bi.wx[k] = lwx[k]; bi.wy[k] = lwy[k]; }
        bi.inv   = (cnt > 0) ? (1.0f / (float)cnt) : 0.0f;
        bi.xbase = xb;
        bi.ybase = yb;
        bi.b     = b;
        sbin[group] = bi;
    }
    __syncthreads();

    // ---------------- Phase 2: unconditional 4x4 gather, clamped, MLP=16 -----
    {
        const BinInfo bi = sbin[group];
        const float4* __restrict__ base =
            reinterpret_cast<const float4*>(g_nhwc)
            + (size_t)bi.b * (HH * WW * (CH / 4)) + c4;

        // Clamped row pointers and x offsets: always in-bounds, always finite,
        // so zero weights cannot introduce NaN/Inf.
        const float4* __restrict__ row[4];
        #pragma unroll
        for (int yi = 0; yi < 4; yi++)
            row[yi] = base + min(bi.ybase + yi, HH - 1) * (WW * (CH / 4));
        int xo[4];
        #pragma unroll
        for (int xi = 0; xi < 4; xi++)
            xo[xi] = min(bi.xbase + xi, WW - 1) * (CH / 4);

        float4 acc = make_float4(0.f, 0.f, 0.f, 0.f);
        #pragma unroll
        for (int yi = 0; yi < 4; yi++) {
            const float wyv = bi.wy[yi];
            float4 racc = make_float4(0.f, 0.f, 0.f, 0.f);
            #pragma unroll
            for (int xi = 0; xi < 4; xi++) {
                const float wxv = bi.wx[xi];
                const float4 v = row[yi][xo[xi]];
                racc.x += wxv * v.x;
                racc.y += wxv * v.y;
                racc.z += wxv * v.z;
                racc.w += wxv * v.w;
            }
            acc.x += wyv * racc.x;
            acc.y += wyv * racc.y;
            acc.z += wyv * racc.z;
            acc.w += wyv * racc.w;
        }
        acc.x *= bi.inv; acc.y *= bi.inv; acc.z *= bi.inv; acc.w *= bi.inv;
        sm4[group * 64 + c4] = acc;     // [pw][c4], STS.128
    }
    __syncthreads();

    // ---------------- Phase 3: near-coalesced output writes -------------------
    // out[n][c][ph][pw] ; smem holds sm[pw*256 + c]
    {
        const float* sm = reinterpret_cast<const float*>(sm4);
        const size_t outbase = (size_t)n * (CH * PP * PP) + (size_t)ph * PP;
        #pragma unroll
        for (int k = 0; k < 4; k++) {
            const int i  = tid + k * 448;      // 0 .. 1791
            const int c  = i / 7;
            const int pw = i % 7;
            out[outbase + (size_t)c * (PP * PP) + pw] = sm[pw * CH + c];
        }
    }
}

extern "C" void kernel_launch(void* const* d_in, const int* in_sizes, int n_in,
                              void* d_out, int out_size) {
    const float* data   = (const float*)d_in[0];   // [4,256,64,64]
    const float* rois   = (const float*)d_in[1];   // [256,5]
    const float* offset = (const float*)d_in[2];   // [256,2,7,7]
    float* out = (float*)d_out;                    // [256,256,7,7]

    dim3 tb(32, 8);
    dim3 tg(WW / 32, CH / 32, BATCH * HH);
    nchw_to_nhwc_kernel<<<tg, tb>>>(data);

    dim3 pg(PP, NROI);                             // (ph, n)
    deform_roi_pool_kernel<<<pg, 448>>>(rois, offset, out);
}